// round 3
// baseline (speedup 1.0000x reference)
#include <cuda_runtime.h>
#include <math.h>

#define Bb 2
#define Tt 2048
#define Dd 1024
#define Hh 16
#define HDd 64
#define Mrows (Bb*Tt)

// Scratch (allocation-free per harness rules)
__device__ float g_Q[Mrows*Dd];
__device__ float g_K[Mrows*Dd];
__device__ float g_V[Mrows*Dd];
__device__ float g_O[Mrows*Dd];
__device__ float g_ksum[Bb*Dd];
__device__ float g_gdiag[Dd];

// ---------------- gdiag[h*64+d] = sum_r A[h,r,d]^2 + exp(log_lambda[h]) ----
__global__ void gdiag_kernel(const float* __restrict__ A, const float* __restrict__ ll) {
    int i = blockIdx.x * blockDim.x + threadIdx.x;
    if (i >= Dd) return;
    int h = i >> 6, d = i & 63;
    float s = 0.f;
#pragma unroll
    for (int r = 0; r < 16; r++) {
        float a = A[(h * 16 + r) * HDd + d];
        s = fmaf(a, a, s);
    }
    g_gdiag[i] = s + __expf(ll[h]);
}

// ---------------- ksum[b, c] = sum_t K[b, t, c] -------------------------
__global__ void ksum_zero_kernel() {
    int i = blockIdx.x * blockDim.x + threadIdx.x;
    if (i < Bb * Dd) g_ksum[i] = 0.f;
}

__global__ void ksum_kernel() {
    int c = blockIdx.x * blockDim.x + threadIdx.x;  // 0..2047
    if (c >= Bb * Dd) return;
    int b = c >> 10;
    int col = c & (Dd - 1);
    int tchunk = blockIdx.y;  // 0..15
    const float* p = g_K + (size_t)b * Tt * Dd + (size_t)tchunk * (Tt / 16) * Dd + col;
    float s = 0.f;
#pragma unroll 4
    for (int t = 0; t < Tt / 16; t++) s += p[(size_t)t * Dd];
    atomicAdd(&g_ksum[c], s);
}

// ---------------- GEMM: C[m,n] = sum_k X[m,k] * W[n,k] + bias[n] ---------
// X: (M,K) row-major, W: (N,K) row-major. 64x64 tile, BK=16, 256 threads, 4x4/thread.
#define GBM 64
#define GBN 64
#define GBK 16

__global__ __launch_bounds__(256) void gemm_nt_bias(
    const float* __restrict__ X, const float* __restrict__ W,
    const float* __restrict__ bias, float* __restrict__ C,
    int M, int N, int K)
{
    __shared__ float As[GBK][GBM + 4];
    __shared__ float Bs[GBK][GBN + 4];
    int tid = threadIdx.x;
    int bm = blockIdx.y * GBM, bn = blockIdx.x * GBN;
    int ty = tid >> 4, tx = tid & 15;
    int lr = tid >> 2;          // 0..63
    int lk = (tid & 3) << 2;    // 0,4,8,12
    const float* Xp = X + (size_t)(bm + lr) * K + lk;
    const float* Wp = W + (size_t)(bn + lr) * K + lk;
    float acc[4][4];
#pragma unroll
    for (int i = 0; i < 4; i++)
#pragma unroll
        for (int j = 0; j < 4; j++) acc[i][j] = 0.f;

    for (int k0 = 0; k0 < K; k0 += GBK) {
        float4 xa = *(const float4*)(Xp + k0);
        float4 wa = *(const float4*)(Wp + k0);
        __syncthreads();
        As[lk + 0][lr] = xa.x; As[lk + 1][lr] = xa.y;
        As[lk + 2][lr] = xa.z; As[lk + 3][lr] = xa.w;
        Bs[lk + 0][lr] = wa.x; Bs[lk + 1][lr] = wa.y;
        Bs[lk + 2][lr] = wa.z; Bs[lk + 3][lr] = wa.w;
        __syncthreads();
#pragma unroll
        for (int k = 0; k < GBK; k++) {
            float4 a = *(const float4*)&As[k][ty << 2];
            float4 b = *(const float4*)&Bs[k][tx << 2];
            float av[4] = {a.x, a.y, a.z, a.w};
            float bv[4] = {b.x, b.y, b.z, b.w};
#pragma unroll
            for (int i = 0; i < 4; i++)
#pragma unroll
                for (int j = 0; j < 4; j++)
                    acc[i][j] = fmaf(av[i], bv[j], acc[i][j]);
        }
    }
    float4 bvv = *(const float4*)&bias[bn + (tx << 2)];
#pragma unroll
    for (int i = 0; i < 4; i++) {
        float4 o;
        o.x = acc[i][0] + bvv.x;
        o.y = acc[i][1] + bvv.y;
        o.z = acc[i][2] + bvv.z;
        o.w = acc[i][3] + bvv.w;
        *(float4*)&C[(size_t)(bm + (ty << 2) + i) * N + bn + (tx << 2)] = o;
    }
}

// ---------------- Flash attention, fp32 ---------------------------------
// Per block: one (b,h), 64 query rows. softmax_j(Sg[t] . k[j]) @ v
__global__ __launch_bounds__(256) void attn_kernel() {
    __shared__ float SgT[64][68];  // [d][r]
    __shared__ float KsT[64][68];  // [d][j]
    __shared__ float Vs[64][68];   // [j][d]
    __shared__ float Ps[64][68];   // [r][j]

    int tid = threadIdx.x;
    int bh = blockIdx.y;
    int b = bh >> 4, h = bh & 15;
    int t0 = blockIdx.x << 6;
    int col0 = h << 6;
    int ty = tid >> 4, tx = tid & 15;

    const float* Qb = g_Q + (size_t)b * Tt * Dd;
    const float* Kb = g_K + (size_t)b * Tt * Dd;
    const float* Vb = g_V + (size_t)b * Tt * Dd;

    // Fill SgT[d][r] = (T*q - ksum) * gdiag
    {
        int r = tid >> 2;
        int dbase = (tid & 3) << 4;
        const float* qrow = Qb + (size_t)(t0 + r) * Dd + col0;
#pragma unroll
        for (int u = 0; u < 4; u++) {
            int d = dbase + (u << 2);
            float4 q4 = *(const float4*)(qrow + d);
            float4 ks = *(const float4*)(g_ksum + b * Dd + col0 + d);
            float4 gd = *(const float4*)(g_gdiag + col0 + d);
            SgT[d + 0][r] = (2048.f * q4.x - ks.x) * gd.x;
            SgT[d + 1][r] = (2048.f * q4.y - ks.y) * gd.y;
            SgT[d + 2][r] = (2048.f * q4.z - ks.z) * gd.z;
            SgT[d + 3][r] = (2048.f * q4.w - ks.w) * gd.w;
        }
    }

    float m[4], l[4], o[4][4];
#pragma unroll
    for (int i = 0; i < 4; i++) {
        m[i] = -1e30f;
        l[i] = 0.f;
#pragma unroll
        for (int j = 0; j < 4; j++) o[i][j] = 0.f;
    }

    for (int j0 = 0; j0 < Tt; j0 += 64) {
        __syncthreads();
        // Load K (transposed) and V tiles
        {
            int r = tid >> 2;
            int dbase = (tid & 3) << 4;
            const float* krow = Kb + (size_t)(j0 + r) * Dd + col0;
            const float* vrow = Vb + (size_t)(j0 + r) * Dd + col0;
#pragma unroll
            for (int u = 0; u < 4; u++) {
                int d = dbase + (u << 2);
                float4 k4 = *(const float4*)(krow + d);
                KsT[d + 0][r] = k4.x; KsT[d + 1][r] = k4.y;
                KsT[d + 2][r] = k4.z; KsT[d + 3][r] = k4.w;
                float4 v4 = *(const float4*)(vrow + d);
                *(float4*)&Vs[r][d] = v4;
            }
        }
        __syncthreads();

        // S[r][j] = sum_d Sg[r][d] * K[j][d]
        float s[4][4];
#pragma unroll
        for (int i = 0; i < 4; i++)
#pragma unroll
            for (int j = 0; j < 4; j++) s[i][j] = 0.f;
#pragma unroll 8
        for (int d = 0; d < 64; d++) {
            float4 a = *(const float4*)&SgT[d][ty << 2];
            float4 bb = *(const float4*)&KsT[d][tx << 2];
            float av[4] = {a.x, a.y, a.z, a.w};
            float bv[4] = {bb.x, bb.y, bb.z, bb.w};
#pragma unroll
            for (int i = 0; i < 4; i++)
#pragma unroll
                for (int j = 0; j < 4; j++)
                    s[i][j] = fmaf(av[i], bv[j], s[i][j]);
        }

        // Online softmax update (row-wise over j; rows split across 16 tx lanes)
#pragma unroll
        for (int ii = 0; ii < 4; ii++) {
            float rm = fmaxf(fmaxf(s[ii][0], s[ii][1]), fmaxf(s[ii][2], s[ii][3]));
#pragma unroll
            for (int w = 1; w < 16; w <<= 1)
                rm = fmaxf(rm, __shfl_xor_sync(0xffffffffu, rm, w));
            float mn = fmaxf(m[ii], rm);
            float sc = __expf(m[ii] - mn);
            m[ii] = mn;
            float p0 = __expf(s[ii][0] - mn);
            float p1 = __expf(s[ii][1] - mn);
            float p2 = __expf(s[ii][2] - mn);
            float p3 = __expf(s[ii][3] - mn);
            float rs = (p0 + p1) + (p2 + p3);
#pragma unroll
            for (int w = 1; w < 16; w <<= 1)
                rs += __shfl_xor_sync(0xffffffffu, rs, w);
            l[ii] = l[ii] * sc + rs;
#pragma unroll
            for (int jj = 0; jj < 4; jj++) o[ii][jj] *= sc;
            *(float4*)&Ps[(ty << 2) + ii][tx << 2] = make_float4(p0, p1, p2, p3);
        }
        __syncthreads();

        // o[r][d] += sum_j P[r][j] * V[j][d]
#pragma unroll 8
        for (int j = 0; j < 64; j++) {
            float4 bb = *(const float4*)&Vs[j][tx << 2];
            float bv[4] = {bb.x, bb.y, bb.z, bb.w};
            float a0 = Ps[(ty << 2) + 0][j];
            float a1 = Ps[(ty << 2) + 1][j];
            float a2 = Ps[(ty << 2) + 2][j];
            float a3 = Ps[(ty << 2) + 3][j];
            float av[4] = {a0, a1, a2, a3};
#pragma unroll
            for (int i = 0; i < 4; i++)
#pragma unroll
                for (int jj = 0; jj < 4; jj++)
                    o[i][jj] = fmaf(av[i], bv[jj], o[i][jj]);
        }
    }

    // Normalize and write O[b, t, h*64+d]
#pragma unroll
    for (int ii = 0; ii < 4; ii++) {
        float inv = 1.f / l[ii];
        float4 o4 = make_float4(o[ii][0] * inv, o[ii][1] * inv,
                                o[ii][2] * inv, o[ii][3] * inv);
        *(float4*)&g_O[(size_t)b * Tt * Dd + (size_t)(t0 + (ty << 2) + ii) * Dd
                       + col0 + (tx << 2)] = o4;
    }
}

// ---------------- launcher ----------------------------------------------
extern "C" void kernel_launch(void* const* d_in, const int* in_sizes, int n_in,
                              void* d_out, int out_size) {
    (void)in_sizes; (void)n_in; (void)out_size;
    const float* x  = (const float*)d_in[0];
    const float* Wq = (const float*)d_in[1];
    const float* bq = (const float*)d_in[2];
    const float* Wk = (const float*)d_in[3];
    const float* bk = (const float*)d_in[4];
    const float* Wv = (const float*)d_in[5];
    const float* bv = (const float*)d_in[6];
    const float* Wo = (const float*)d_in[7];
    const float* bo = (const float*)d_in[8];
    const float* A  = (const float*)d_in[9];
    const float* ll = (const float*)d_in[10];
    float* out = (float*)d_out;

    float *Q, *K, *V, *O;
    cudaGetSymbolAddress((void**)&Q, g_Q);
    cudaGetSymbolAddress((void**)&K, g_K);
    cudaGetSymbolAddress((void**)&V, g_V);
    cudaGetSymbolAddress((void**)&O, g_O);

    dim3 gg(Dd / GBN, Mrows / GBM);  // (16, 64)
    gemm_nt_bias<<<gg, 256>>>(x, Wq, bq, Q, Mrows, Dd, Dd);
    gemm_nt_bias<<<gg, 256>>>(x, Wk, bk, K, Mrows, Dd, Dd);
    gemm_nt_bias<<<gg, 256>>>(x, Wv, bv, V, Mrows, Dd, Dd);

    gdiag_kernel<<<(Dd + 255) / 256, 256>>>(A, ll);
    ksum_zero_kernel<<<(Bb * Dd + 255) / 256, 256>>>();
    ksum_kernel<<<dim3((Bb * Dd + 255) / 256, 16), 256>>>();

    attn_kernel<<<dim3(Tt / 64, Bb * Hh), 256>>>();

    gemm_nt_bias<<<gg, 256>>>(O, Wo, bo, out, Mrows, Dd, Dd);
}

// round 6
// speedup vs baseline: 1.6485x; 1.6485x over previous
#include <cuda_runtime.h>
#include <math.h>

#define Bb 2
#define Tt 2048
#define Dd 1024
#define Hh 16
#define HDd 64
#define Mrows (Bb*Tt)

// Scratch (allocation-free per harness rules)
__device__ float g_Q[Mrows*Dd];
__device__ float g_K[Mrows*Dd];
__device__ float g_V[Mrows*Dd];
__device__ float g_O[Mrows*Dd];
__device__ float g_ksum[Bb*Dd];
__device__ float g_gdiag[Dd];

// ---------------- gdiag[h*64+d] = sum_r A[h,r,d]^2 + exp(log_lambda[h]) ----
__global__ void gdiag_kernel(const float* __restrict__ A, const float* __restrict__ ll) {
    int i = blockIdx.x * blockDim.x + threadIdx.x;
    if (i >= Dd) return;
    int h = i >> 6, d = i & 63;
    float s = 0.f;
#pragma unroll
    for (int r = 0; r < 16; r++) {
        float a = A[(h * 16 + r) * HDd + d];
        s = fmaf(a, a, s);
    }
    g_gdiag[i] = s + __expf(ll[h]);
}

// ---------------- ksum[b, c] = sum_t K[b, t, c] -------------------------
__global__ void ksum_zero_kernel() {
    int i = blockIdx.x * blockDim.x + threadIdx.x;
    if (i < Bb * Dd) g_ksum[i] = 0.f;
}

__global__ void ksum_kernel() {
    int c = blockIdx.x * blockDim.x + threadIdx.x;  // 0..2047
    if (c >= Bb * Dd) return;
    int b = c >> 10;
    int col = c & (Dd - 1);
    int tchunk = blockIdx.y;  // 0..15
    const float* p = g_K + (size_t)b * Tt * Dd + (size_t)tchunk * (Tt / 16) * Dd + col;
    float s = 0.f;
#pragma unroll 4
    for (int t = 0; t < Tt / 16; t++) s += p[(size_t)t * Dd];
    atomicAdd(&g_ksum[c], s);
}

// ---------------- GEMM: C[m,n] = sum_k X[m,k] * W[n,k] + bias[n] ---------
// X: (M,K) row-major, W: (N,K) row-major. 64x64 tile, BK=16, 256 threads, 4x4/thread.
#define GBM 64
#define GBN 64
#define GBK 16

__global__ __launch_bounds__(256) void gemm_nt_bias(
    const float* __restrict__ X, const float* __restrict__ W,
    const float* __restrict__ bias, float* __restrict__ C,
    int M, int N, int K)
{
    __shared__ float As[GBK][GBM + 4];
    __shared__ float Bs[GBK][GBN + 4];
    int tid = threadIdx.x;
    int bm = blockIdx.y * GBM, bn = blockIdx.x * GBN;
    int ty = tid >> 4, tx = tid & 15;
    int lr = tid >> 2;          // 0..63
    int lk = (tid & 3) << 2;    // 0,4,8,12
    const float* Xp = X + (size_t)(bm + lr) * K + lk;
    const float* Wp = W + (size_t)(bn + lr) * K + lk;
    float acc[4][4];
#pragma unroll
    for (int i = 0; i < 4; i++)
#pragma unroll
        for (int j = 0; j < 4; j++) acc[i][j] = 0.f;

    for (int k0 = 0; k0 < K; k0 += GBK) {
        float4 xa = *(const float4*)(Xp + k0);
        float4 wa = *(const float4*)(Wp + k0);
        __syncthreads();
        As[lk + 0][lr] = xa.x; As[lk + 1][lr] = xa.y;
        As[lk + 2][lr] = xa.z; As[lk + 3][lr] = xa.w;
        Bs[lk + 0][lr] = wa.x; Bs[lk + 1][lr] = wa.y;
        Bs[lk + 2][lr] = wa.z; Bs[lk + 3][lr] = wa.w;
        __syncthreads();
#pragma unroll
        for (int k = 0; k < GBK; k++) {
            float4 a = *(const float4*)&As[k][ty << 2];
            float4 b = *(const float4*)&Bs[k][tx << 2];
            float av[4] = {a.x, a.y, a.z, a.w};
            float bv[4] = {b.x, b.y, b.z, b.w};
#pragma unroll
            for (int i = 0; i < 4; i++)
#pragma unroll
                for (int j = 0; j < 4; j++)
                    acc[i][j] = fmaf(av[i], bv[j], acc[i][j]);
        }
    }
    float4 bvv = *(const float4*)&bias[bn + (tx << 2)];
#pragma unroll
    for (int i = 0; i < 4; i++) {
        float4 o;
        o.x = acc[i][0] + bvv.x;
        o.y = acc[i][1] + bvv.y;
        o.z = acc[i][2] + bvv.z;
        o.w = acc[i][3] + bvv.w;
        *(float4*)&C[(size_t)(bm + (ty << 2) + i) * N + bn + (tx << 2)] = o;
    }
}

// ---------------- Flash attention, fp32 ---------------------------------
// Per block: one (b,h), 64 query rows. softmax_j(Sg[t] . k[j]) @ v
__global__ __launch_bounds__(256) void attn_kernel() {
    __shared__ float SgT[64][68];  // [d][r]
    __shared__ float KsT[64][68];  // [d][j]
    __shared__ float Vs[64][68];   // [j][d]
    __shared__ float Ps[64][68];   // [r][j]

    int tid = threadIdx.x;
    int bh = blockIdx.y;
    int b = bh >> 4, h = bh & 15;
    int t0 = blockIdx.x << 6;
    int col0 = h << 6;
    int ty = tid >> 4, tx = tid & 15;

    const float* Qb = g_Q + (size_t)b * Tt * Dd;
    const float* Kb = g_K + (size_t)b * Tt * Dd;
    const float* Vb = g_V + (size_t)b * Tt * Dd;

    // Fill SgT[d][r] = (T*q - ksum) * gdiag
    {
        int r = tid >> 2;
        int dbase = (tid & 3) << 4;
        const float* qrow = Qb + (size_t)(t0 + r) * Dd + col0;
#pragma unroll
        for (int u = 0; u < 4; u++) {
            int d = dbase + (u << 2);
            float4 q4 = *(const float4*)(qrow + d);
            float4 ks = *(const float4*)(g_ksum + b * Dd + col0 + d);
            float4 gd = *(const float4*)(g_gdiag + col0 + d);
            SgT[d + 0][r] = (2048.f * q4.x - ks.x) * gd.x;
            SgT[d + 1][r] = (2048.f * q4.y - ks.y) * gd.y;
            SgT[d + 2][r] = (2048.f * q4.z - ks.z) * gd.z;
            SgT[d + 3][r] = (2048.f * q4.w - ks.w) * gd.w;
        }
    }

    float m[4], l[4], o[4][4];
#pragma unroll
    for (int i = 0; i < 4; i++) {
        m[i] = -1e30f;
        l[i] = 0.f;
#pragma unroll
        for (int j = 0; j < 4; j++) o[i][j] = 0.f;
    }

    for (int j0 = 0; j0 < Tt; j0 += 64) {
        __syncthreads();
        // Load K (transposed) and V tiles
        {
            int r = tid >> 2;
            int dbase = (tid & 3) << 4;
            const float* krow = Kb + (size_t)(j0 + r) * Dd + col0;
            const float* vrow = Vb + (size_t)(j0 + r) * Dd + col0;
#pragma unroll
            for (int u = 0; u < 4; u++) {
                int d = dbase + (u << 2);
                float4 k4 = *(const float4*)(krow + d);
                KsT[d + 0][r] = k4.x; KsT[d + 1][r] = k4.y;
                KsT[d + 2][r] = k4.z; KsT[d + 3][r] = k4.w;
                float4 v4 = *(const float4*)(vrow + d);
                *(float4*)&Vs[r][d] = v4;
            }
        }
        __syncthreads();

        // S[r][j] = sum_d Sg[r][d] * K[j][d]
        float s[4][4];
#pragma unroll
        for (int i = 0; i < 4; i++)
#pragma unroll
            for (int j = 0; j < 4; j++) s[i][j] = 0.f;
#pragma unroll 8
        for (int d = 0; d < 64; d++) {
            float4 a = *(const float4*)&SgT[d][ty << 2];
            float4 bb = *(const float4*)&KsT[d][tx << 2];
            float av[4] = {a.x, a.y, a.z, a.w};
            float bv[4] = {bb.x, bb.y, bb.z, bb.w};
#pragma unroll
            for (int i = 0; i < 4; i++)
#pragma unroll
                for (int j = 0; j < 4; j++)
                    s[i][j] = fmaf(av[i], bv[j], s[i][j]);
        }

        // Online softmax update (row-wise over j; rows split across 16 tx lanes)
#pragma unroll
        for (int ii = 0; ii < 4; ii++) {
            float rm = fmaxf(fmaxf(s[ii][0], s[ii][1]), fmaxf(s[ii][2], s[ii][3]));
#pragma unroll
            for (int w = 1; w < 16; w <<= 1)
                rm = fmaxf(rm, __shfl_xor_sync(0xffffffffu, rm, w));
            float mn = fmaxf(m[ii], rm);
            float sc = __expf(m[ii] - mn);
            m[ii] = mn;
            float p0 = __expf(s[ii][0] - mn);
            float p1 = __expf(s[ii][1] - mn);
            float p2 = __expf(s[ii][2] - mn);
            float p3 = __expf(s[ii][3] - mn);
            float rs = (p0 + p1) + (p2 + p3);
#pragma unroll
            for (int w = 1; w < 16; w <<= 1)
                rs += __shfl_xor_sync(0xffffffffu, rs, w);
            l[ii] = l[ii] * sc + rs;
#pragma unroll
            for (int jj = 0; jj < 4; jj++) o[ii][jj] *= sc;
            *(float4*)&Ps[(ty << 2) + ii][tx << 2] = make_float4(p0, p1, p2, p3);
        }
        __syncthreads();

        // o[r][d] += sum_j P[r][j] * V[j][d]
#pragma unroll 8
        for (int j = 0; j < 64; j++) {
            float4 bb = *(const float4*)&Vs[j][tx << 2];
            float bv[4] = {bb.x, bb.y, bb.z, bb.w};
            float a0 = Ps[(ty << 2) + 0][j];
            float a1 = Ps[(ty << 2) + 1][j];
            float a2 = Ps[(ty << 2) + 2][j];
            float a3 = Ps[(ty << 2) + 3][j];
            float av[4] = {a0, a1, a2, a3};
#pragma unroll
            for (int i = 0; i < 4; i++)
#pragma unroll
                for (int jj = 0; jj < 4; jj++)
                    o[i][jj] = fmaf(av[i], bv[jj], o[i][jj]);
        }
    }

    // Normalize and write O[b, t, h*64+d]
#pragma unroll
    for (int ii = 0; ii < 4; ii++) {
        float inv = 1.f / l[ii];
        float4 o4 = make_float4(o[ii][0] * inv, o[ii][1] * inv,
                                o[ii][2] * inv, o[ii][3] * inv);
        *(float4*)&g_O[(size_t)b * Tt * Dd + (size_t)(t0 + (ty << 2) + ii) * Dd
                       + col0 + (tx << 2)] = o4;
    }
}

// ---------------- launcher ----------------------------------------------
extern "C" void kernel_launch(void* const* d_in, const int* in_sizes, int n_in,
                              void* d_out, int out_size) {
    (void)in_sizes; (void)n_in; (void)out_size;
    const float* x  = (const float*)d_in[0];
    const float* Wq = (const float*)d_in[1];
    const float* bq = (const float*)d_in[2];
    const float* Wk = (const float*)d_in[3];
    const float* bk = (const float*)d_in[4];
    const float* Wv = (const float*)d_in[5];
    const float* bv = (const float*)d_in[6];
    const float* Wo = (const float*)d_in[7];
    const float* bo = (const float*)d_in[8];
    const float* A  = (const float*)d_in[9];
    const float* ll = (const float*)d_in[10];
    float* out = (float*)d_out;

    float *Q, *K, *V, *O;
    cudaGetSymbolAddress((void**)&Q, g_Q);
    cudaGetSymbolAddress((void**)&K, g_K);
    cudaGetSymbolAddress((void**)&V, g_V);
    cudaGetSymbolAddress((void**)&O, g_O);

    dim3 gg(Dd / GBN, Mrows / GBM);  // (16, 64)
    gemm_nt_bias<<<gg, 256>>>(x, Wq, bq, Q, Mrows, Dd, Dd);
    gemm_nt_bias<<<gg, 256>>>(x, Wk, bk, K, Mrows, Dd, Dd);
    gemm_nt_bias<<<gg, 256>>>(x, Wv, bv, V, Mrows, Dd, Dd);

    gdiag_kernel<<<(Dd + 255) / 256, 256>>>(A, ll);
    ksum_zero_kernel<<<(Bb * Dd + 255) / 256, 256>>>();
    ksum_kernel<<<dim3((Bb * Dd + 255) / 256, 16), 256>>>();

    attn_kernel<<<dim3(Tt / 64, Bb * Hh), 256>>>();

    gemm_nt_bias<<<gg, 256>>>(O, Wo, bo, out, Mrows, Dd, Dd);
}